// round 3
// baseline (speedup 1.0000x reference)
#include <cuda_runtime.h>
#include <math.h>

// Problem constants
static const int Bc  = 2;
static const int Tc  = 2048;
static const int Dc  = 512;
static const int Hc  = 8;
static const int BT  = Bc * Tc;      // 4096
static const int BHc = Bc * Hc;      // 16

// Scratch (device globals: no allocation allowed)
__device__ float g_Q[BHc * Tc * 64];   // [B,H,T,DK]
__device__ float g_K[BHc * Tc * 64];
__device__ float g_V[BHc * Tc * 64];
__device__ float g_Oh[BT * Dc];        // attention output in [B,T,D] layout

// ---------------------------------------------------------------------------
// TF32 helpers
// ---------------------------------------------------------------------------
__device__ __forceinline__ unsigned tf32u(float x) {
    unsigned u; asm("cvt.rna.tf32.f32 %0, %1;" : "=r"(u) : "f"(x)); return u;
}
__device__ __forceinline__ float tf32f(float x) { return __uint_as_float(tf32u(x)); }

// split v into (big, res) tf32 pair
__device__ __forceinline__ void split2(float v, float& b, float& r) {
    b = tf32f(v); r = tf32f(v - b);
}
// pack a float4 into two interleaved float4s {b0,r0,b1,r1},{b2,r2,b3,r3}
__device__ __forceinline__ void split4i(float4 v, float4& p0, float4& p1) {
    split2(v.x, p0.x, p0.y); split2(v.y, p0.z, p0.w);
    split2(v.z, p1.x, p1.y); split2(v.w, p1.z, p1.w);
}

// D += A(16x8,row) * B(8x8,col)  tf32, fp32 acc
__device__ __forceinline__ void mma8(float* c, const unsigned* a, const unsigned* b) {
    asm volatile(
        "mma.sync.aligned.m16n8k8.row.col.f32.tf32.tf32.f32 "
        "{%0,%1,%2,%3},{%4,%5,%6,%7},{%8,%9},{%0,%1,%2,%3};"
        : "+f"(c[0]), "+f"(c[1]), "+f"(c[2]), "+f"(c[3])
        : "r"(a[0]), "r"(a[1]), "r"(a[2]), "r"(a[3]), "r"(b[0]), "r"(b[1]));
}

// ---------------------------------------------------------------------------
// Projection GEMM body (tf32x3):  Y[m,n] = sum_k X[m,k]*W[n,k] + bias[n]
// M=4096, N=512, K=512. Block tile 128x64, 256 threads (8 warps, 4x2),
// warp tile 32x32. Smem holds interleaved (big,res) pairs:
//   Xi[128][72]  (k*2 + {0,1}, 64 data + 8 pad floats)
//   Wi[64][72]
// ---------------------------------------------------------------------------
static const int PJ_XI = 0;
static const int PJ_WI = 128 * 72;                   // 9216
static const int PJ_SMEM_FLOATS = PJ_WI + 64 * 72;   // 13824
static const int PJ_SMEM_BYTES  = PJ_SMEM_FLOATS * 4;// 55296

__device__ __forceinline__ void proj_body(
    const float* __restrict__ X, const float* __restrict__ W,
    const float* __restrict__ bias, float* __restrict__ Y, int head_layout,
    float* ps)
{
    float* Xi = ps + PJ_XI;
    float* Wi = ps + PJ_WI;

    const int tid  = threadIdx.x;
    const int lane = tid & 31;
    const int w    = tid >> 5;
    const int g    = lane >> 2;    // 0..7
    const int t4   = lane & 3;     // 0..3
    const int m0 = blockIdx.y * 128;
    const int n0 = blockIdx.x * 64;
    const int wm = (w & 3) * 32;
    const int wn = (w >> 2) * 32;

    float acc[2][4][4];
    #pragma unroll
    for (int i = 0; i < 2; i++)
        #pragma unroll
        for (int j = 0; j < 4; j++)
            #pragma unroll
            for (int l = 0; l < 4; l++) acc[i][j][l] = 0.f;

    // per-thread tile coords for loads
    const int xr_ = tid >> 3, xc_ = tid & 7;   // X: rows via +32/p, cols c4

    float4 xv[4], wv[2];
    #pragma unroll
    for (int p = 0; p < 4; p++)
        xv[p] = *(const float4*)(X + (size_t)(m0 + xr_ + p * 32) * 512 + xc_ * 4);
    #pragma unroll
    for (int p = 0; p < 2; p++)
        wv[p] = *(const float4*)(W + (size_t)(n0 + xr_ + p * 32) * 512 + xc_ * 4);

    for (int k0 = 0; k0 < 512; k0 += 32) {
        __syncthreads();
        #pragma unroll
        for (int p = 0; p < 4; p++) {
            float4 p0, p1; split4i(xv[p], p0, p1);
            float* dst = Xi + (xr_ + p * 32) * 72 + xc_ * 8;
            *(float4*)dst = p0; *(float4*)(dst + 4) = p1;
        }
        #pragma unroll
        for (int p = 0; p < 2; p++) {
            float4 p0, p1; split4i(wv[p], p0, p1);
            float* dst = Wi + (xr_ + p * 32) * 72 + xc_ * 8;
            *(float4*)dst = p0; *(float4*)(dst + 4) = p1;
        }
        __syncthreads();

        if (k0 + 32 < 512) {
            #pragma unroll
            for (int p = 0; p < 4; p++)
                xv[p] = *(const float4*)(X + (size_t)(m0 + xr_ + p * 32) * 512 + k0 + 32 + xc_ * 4);
            #pragma unroll
            for (int p = 0; p < 2; p++)
                wv[p] = *(const float4*)(W + (size_t)(n0 + xr_ + p * 32) * 512 + k0 + 32 + xc_ * 4);
        }

        #pragma unroll
        for (int ks = 0; ks < 4; ks++) {
            int kk = ks * 8;
            unsigned ab[2][4], ar[2][4];
            #pragma unroll
            for (int mt = 0; mt < 2; mt++) {
                int rr = wm + mt * 16 + g;
                float2 p00 = *(const float2*)(Xi + rr * 72 + (kk + t4) * 2);
                float2 p10 = *(const float2*)(Xi + (rr + 8) * 72 + (kk + t4) * 2);
                float2 p01 = *(const float2*)(Xi + rr * 72 + (kk + t4 + 4) * 2);
                float2 p11 = *(const float2*)(Xi + (rr + 8) * 72 + (kk + t4 + 4) * 2);
                ab[mt][0] = __float_as_uint(p00.x); ar[mt][0] = __float_as_uint(p00.y);
                ab[mt][1] = __float_as_uint(p10.x); ar[mt][1] = __float_as_uint(p10.y);
                ab[mt][2] = __float_as_uint(p01.x); ar[mt][2] = __float_as_uint(p01.y);
                ab[mt][3] = __float_as_uint(p11.x); ar[mt][3] = __float_as_uint(p11.y);
            }
            #pragma unroll
            for (int nt = 0; nt < 4; nt++) {
                int nn = wn + nt * 8 + g;
                float2 q0 = *(const float2*)(Wi + nn * 72 + (kk + t4) * 2);
                float2 q1 = *(const float2*)(Wi + nn * 72 + (kk + t4 + 4) * 2);
                unsigned bb[2] = { __float_as_uint(q0.x), __float_as_uint(q1.x) };
                unsigned br[2] = { __float_as_uint(q0.y), __float_as_uint(q1.y) };
                #pragma unroll
                for (int mt = 0; mt < 2; mt++) {
                    mma8(acc[mt][nt], ab[mt], bb);
                    mma8(acc[mt][nt], ab[mt], br);
                    mma8(acc[mt][nt], ar[mt], bb);
                }
            }
        }
    }

    // epilogue
    #pragma unroll
    for (int mt = 0; mt < 2; mt++) {
        #pragma unroll
        for (int nt = 0; nt < 4; nt++) {
            int r0 = m0 + wm + mt * 16 + g;
            int c0 = n0 + wn + nt * 8 + t4 * 2;
            #pragma unroll
            for (int e = 0; e < 4; e++) {
                int m = r0 + (e >= 2 ? 8 : 0);
                int n = c0 + (e & 1);
                float v = acc[mt][nt][e] + bias[n];
                if (head_layout) {
                    int bb2 = m >> 11, t = m & 2047;
                    int h = n >> 6, dk = n & 63;
                    Y[(((size_t)(bb2 * Hc + h) * Tc + t) * 64) + dk] = v;
                } else {
                    Y[(size_t)m * Dc + n] = v;
                }
            }
        }
    }
}

__global__ void __launch_bounds__(256) qkv_proj(
    const float* __restrict__ q, const float* __restrict__ Wq, const float* __restrict__ bq,
    const float* __restrict__ k, const float* __restrict__ Wk, const float* __restrict__ bk,
    const float* __restrict__ v, const float* __restrict__ Wv, const float* __restrict__ bv)
{
    extern __shared__ float ps[];
    int z = blockIdx.z;
    const float* X = (z == 0) ? q : (z == 1) ? k : v;
    const float* W = (z == 0) ? Wq : (z == 1) ? Wk : Wv;
    const float* B = (z == 0) ? bq : (z == 1) ? bk : bv;
    float* Y = (z == 0) ? g_Q : (z == 1) ? g_K : g_V;
    proj_body(X, W, B, Y, 1, ps);
}

__global__ void __launch_bounds__(256) out_proj(
    const float* __restrict__ W, const float* __restrict__ bias, float* __restrict__ Y)
{
    extern __shared__ float ps[];
    proj_body(g_Oh, W, bias, Y, 0, ps);
}

// ---------------------------------------------------------------------------
// Fused attention (tensor-core): per (bh, 16-query tile).
// Smem (floats):
//   S  [16][2052]  exp scores (fp32)
//   Qi [16][136]   Q tile, (big,res) interleaved tf32x3
//   Ki [128][136]  K chunk, (big,res) interleaved (V [128][72] overlays this)
// ---------------------------------------------------------------------------
static const int SST = 2052;
static const int AT_QI = 16 * SST;            // 32832
static const int AT_KI = AT_QI + 16 * 136;    // 35008
static const int AT_SMEM_FLOATS = AT_KI + 128 * 136;   // 52416
static const int AT_SMEM_BYTES  = AT_SMEM_FLOATS * 4;  // 209664

__global__ void __launch_bounds__(256) attn_mma(float* __restrict__ Aout)
{
    extern __shared__ float sm[];
    float* S  = sm;
    float* Qi = sm + AT_QI;
    float* Ki = sm + AT_KI;
    float* Vs = sm + AT_KI;      // V overlays Ki (used after QK^T of each chunk)
    __shared__ float sinv[16];

    const int tid  = threadIdx.x;
    const int lane = tid & 31;
    const int w    = tid >> 5;     // 0..7
    const int g    = lane >> 2;    // 0..7
    const int t4   = lane & 3;     // 0..3
    const int bh   = blockIdx.y;
    const int q0   = blockIdx.x * 16;

    const float4* Qg = (const float4*)(g_Q + (size_t)bh * Tc * 64);
    const float4* Kg = (const float4*)(g_K + (size_t)bh * Tc * 64);
    const float4* Vg = (const float4*)(g_V + (size_t)bh * Tc * 64);

    // Q tile: 16q x 16(d/4), one float4 per thread, scaled by 1/8, split+interleave
    {
        int qq = tid >> 4, d4 = tid & 15;
        float4 qv = Qg[(size_t)(q0 + qq) * 16 + d4];
        qv.x *= 0.125f; qv.y *= 0.125f; qv.z *= 0.125f; qv.w *= 0.125f;
        float4 p0, p1; split4i(qv, p0, p1);
        float* dst = Qi + qq * 136 + d4 * 8;
        *(float4*)dst = p0; *(float4*)(dst + 4) = p1;
    }

    const int nch   = (q0 + 16 + 127) >> 7;
    const int kceil = nch << 7;

    const int ldr = tid >> 4;      // 0..15 (key sub-row for loads)
    const int ldc = tid & 15;      // 0..15 (d/4)

    float o[4] = {0.f, 0.f, 0.f, 0.f};

    for (int ch = 0; ch < nch; ch++) {
        int kb = ch << 7;

        // prefetch K chunk into regs (no smem dependence)
        float4 kreg[8];
        #pragma unroll
        for (int p = 0; p < 8; p++)
            kreg[p] = Kg[(size_t)(kb + ldr + p * 16) * 16 + ldc];

        __syncthreads();   // prev PV done reading Vs/S; Qi visible after 1st pair
        #pragma unroll
        for (int p = 0; p < 8; p++) {
            float4 p0, p1; split4i(kreg[p], p0, p1);
            float* dst = Ki + (ldr + p * 16) * 136 + ldc * 8;
            *(float4*)dst = p0; *(float4*)(dst + 4) = p1;
        }
        __syncthreads();

        // prefetch V chunk into regs (consumed after next sync)
        float4 vreg[8];
        #pragma unroll
        for (int p = 0; p < 8; p++)
            vreg[p] = Vg[(size_t)(kb + ldr + p * 16) * 16 + ldc];

        // QK^T: warp w owns keys [w*16, w*16+16) -> 2 n-tiles
        float acc[2][4] = {{0.f,0.f,0.f,0.f},{0.f,0.f,0.f,0.f}};
        #pragma unroll
        for (int ks = 0; ks < 8; ks++) {
            int kk = ks * 8;
            float2 p00 = *(const float2*)(Qi + g * 136 + (kk + t4) * 2);
            float2 p10 = *(const float2*)(Qi + (g + 8) * 136 + (kk + t4) * 2);
            float2 p01 = *(const float2*)(Qi + g * 136 + (kk + t4 + 4) * 2);
            float2 p11 = *(const float2*)(Qi + (g + 8) * 136 + (kk + t4 + 4) * 2);
            unsigned ab[4] = { __float_as_uint(p00.x), __float_as_uint(p10.x),
                               __float_as_uint(p01.x), __float_as_uint(p11.x) };
            unsigned ar[4] = { __float_as_uint(p00.y), __float_as_uint(p10.y),
                               __float_as_uint(p01.y), __float_as_uint(p11.y) };
            #pragma unroll
            for (int nt = 0; nt < 2; nt++) {
                int key0 = w * 16 + nt * 8 + g;
                float2 q0f = *(const float2*)(Ki + key0 * 136 + (kk + t4) * 2);
                float2 q1f = *(const float2*)(Ki + key0 * 136 + (kk + t4 + 4) * 2);
                unsigned bb[2] = { __float_as_uint(q0f.x), __float_as_uint(q1f.x) };
                unsigned br[2] = { __float_as_uint(q0f.y), __float_as_uint(q1f.y) };
                mma8(acc[nt], ab, bb);
                mma8(acc[nt], ab, br);
                mma8(acc[nt], ar, bb);
            }
        }

        // exp + causal mask + store e into S
        #pragma unroll
        for (int nt = 0; nt < 2; nt++) {
            int kloc = w * 16 + nt * 8 + t4 * 2;
            int kg = kb + kloc;
            int r0 = g, r1 = g + 8;
            float e0 = (kg     <= q0 + r0) ? __expf(acc[nt][0]) : 0.f;
            float e1 = (kg + 1 <= q0 + r0) ? __expf(acc[nt][1]) : 0.f;
            float e2 = (kg     <= q0 + r1) ? __expf(acc[nt][2]) : 0.f;
            float e3 = (kg + 1 <= q0 + r1) ? __expf(acc[nt][3]) : 0.f;
            S[r0 * SST + kb + kloc]     = e0;
            S[r0 * SST + kb + kloc + 1] = e1;
            S[r1 * SST + kb + kloc]     = e2;
            S[r1 * SST + kb + kloc + 1] = e3;
        }
        __syncthreads();   // all QK reads of Ki done; e visible

        // V chunk into Vs (plain tf32, vectorized)
        #pragma unroll
        for (int p = 0; p < 8; p++) {
            float4 vv = vreg[p];
            float4 tv = make_float4(tf32f(vv.x), tf32f(vv.y), tf32f(vv.z), tf32f(vv.w));
            *(float4*)(Vs + (ldr + p * 16) * 72 + ldc * 4) = tv;
        }
        __syncthreads();

        // PV: warp w owns dk strip [w*8, w*8+8)
        const int d = w * 8 + g;
        #pragma unroll
        for (int ks = 0; ks < 16; ks++) {
            int kk = ks * 8;
            unsigned a[4];
            a[0] = tf32u(S[g * SST + kb + kk + t4]);
            a[1] = tf32u(S[(g + 8) * SST + kb + kk + t4]);
            a[2] = tf32u(S[g * SST + kb + kk + t4 + 4]);
            a[3] = tf32u(S[(g + 8) * SST + kb + kk + t4 + 4]);
            unsigned b[2] = { __float_as_uint(Vs[(kk + t4) * 72 + d]),
                              __float_as_uint(Vs[(kk + t4 + 4) * 72 + d]) };
            mma8(o, a, b);
        }
    }
    __syncthreads();

    // row sums -> sinv
    {
        int rr = tid >> 4, l = tid & 15;
        const float4* Sr = (const float4*)(S + rr * SST);
        float s = 0.f;
        for (int c4 = l; c4 < (kceil >> 2); c4 += 16) {
            float4 f = Sr[c4];
            s += (f.x + f.y) + (f.z + f.w);
        }
        #pragma unroll
        for (int off = 8; off; off >>= 1)
            s += __shfl_xor_sync(0xffffffffu, s, off, 16);
        if (l == 0) sinv[rr] = 1.f / s;
    }
    __syncthreads();

    // O write (normalized) -> g_Oh [B,T,D]
    {
        int bb2 = bh >> 3, hh = bh & 7;
        int dk = w * 8 + t4 * 2;
        float* Od = g_Oh + ((size_t)(bb2 * Tc + q0)) * Dc + hh * 64;
        Od[(size_t)g * Dc + dk]           = o[0] * sinv[g];
        Od[(size_t)g * Dc + dk + 1]       = o[1] * sinv[g];
        Od[(size_t)(g + 8) * Dc + dk]     = o[2] * sinv[g + 8];
        Od[(size_t)(g + 8) * Dc + dk + 1] = o[3] * sinv[g + 8];
    }

    // A write (full 2048 width; zeros past kceil; masked already zeroed)
    if (Aout) {
        float4* A4 = (float4*)(Aout + (size_t)bh * Tc * Tc + (size_t)q0 * Tc);
        int kc4 = kceil >> 2;
        for (int idx = tid; idx < 16 * 512; idx += 256) {
            int qq = idx >> 9, c4 = idx & 511;
            float4 ov;
            if (c4 < kc4) {
                float4 e4 = *(const float4*)(S + qq * SST + c4 * 4);
                float inv = sinv[qq];
                ov = make_float4(e4.x * inv, e4.y * inv, e4.z * inv, e4.w * inv);
            } else {
                ov = make_float4(0.f, 0.f, 0.f, 0.f);
            }
            A4[(size_t)qq * 512 + c4] = ov;
        }
    }
}

// ---------------------------------------------------------------------------
extern "C" void kernel_launch(void* const* d_in, const int* in_sizes, int n_in,
                              void* d_out, int out_size)
{
    const float* q  = (const float*)d_in[0];
    const float* k  = (const float*)d_in[1];
    const float* v  = (const float*)d_in[2];
    // d_in[3] = attn_mask (deterministic causal tril; applied analytically)
    const float* Wq = (const float*)d_in[4];
    const float* bq = (const float*)d_in[5];
    const float* Wk = (const float*)d_in[6];
    const float* bk = (const float*)d_in[7];
    const float* Wv = (const float*)d_in[8];
    const float* bv = (const float*)d_in[9];
    const float* Wo = (const float*)d_in[10];
    const float* bo = (const float*)d_in[11];

    float* out = (float*)d_out;
    long long need = (long long)BT * Dc + (long long)BHc * Tc * Tc;
    float* A = ((long long)out_size >= need) ? out + (size_t)BT * Dc : nullptr;

    cudaFuncSetAttribute(qkv_proj,
                         cudaFuncAttributeMaxDynamicSharedMemorySize, PJ_SMEM_BYTES);
    cudaFuncSetAttribute(out_proj,
                         cudaFuncAttributeMaxDynamicSharedMemorySize, PJ_SMEM_BYTES);
    cudaFuncSetAttribute(attn_mma,
                         cudaFuncAttributeMaxDynamicSharedMemorySize, AT_SMEM_BYTES);

    dim3 pg3(Dc / 64, BT / 128, 3);   // (8, 32, 3)
    qkv_proj<<<pg3, 256, PJ_SMEM_BYTES>>>(q, Wq, bq, k, Wk, bk, v, Wv, bv);

    dim3 ag(Tc / 16, BHc);            // (128, 16)
    attn_mma<<<ag, 256, AT_SMEM_BYTES>>>(A);

    dim3 pg(Dc / 64, BT / 128);       // (8, 32)
    out_proj<<<pg, 256, PJ_SMEM_BYTES>>>(Wo, bo, out);
}

// round 4
// speedup vs baseline: 1.9909x; 1.9909x over previous
#include <cuda_runtime.h>
#include <cuda_fp16.h>
#include <math.h>

// Problem constants
static const int Bc  = 2;
static const int Tc  = 2048;
static const int Dc  = 512;
static const int Hc  = 8;
static const int BT  = Bc * Tc;      // 4096
static const int BHc = Bc * Hc;      // 16

// Scratch (device globals)
__device__ float g_Q[BHc * Tc * 64];   // [B,H,T,DK]
__device__ float g_K[BHc * Tc * 64];
__device__ float g_V[BHc * Tc * 64];
__device__ float g_Oh[BT * Dc];        // attention output [B,T,D]

// ---------------------------------------------------------------------------
// helpers
// ---------------------------------------------------------------------------
__device__ __forceinline__ unsigned sptr(const void* p) {
    return (unsigned)__cvta_generic_to_shared(p);
}
__device__ __forceinline__ void ldm4(unsigned* r, unsigned addr) {
    asm volatile("ldmatrix.sync.aligned.m8n8.x4.shared.b16 {%0,%1,%2,%3}, [%4];"
        : "=r"(r[0]), "=r"(r[1]), "=r"(r[2]), "=r"(r[3]) : "r"(addr));
}
__device__ __forceinline__ void ldm4t(unsigned* r, unsigned addr) {
    asm volatile("ldmatrix.sync.aligned.m8n8.x4.trans.shared.b16 {%0,%1,%2,%3}, [%4];"
        : "=r"(r[0]), "=r"(r[1]), "=r"(r[2]), "=r"(r[3]) : "r"(addr));
}
// D += A(16x16) * B(16x8), fp16 in, fp32 acc
__device__ __forceinline__ void mma16(float* c, const unsigned* a, const unsigned* b) {
    asm volatile(
        "mma.sync.aligned.m16n8k16.row.col.f32.f16.f16.f32 "
        "{%0,%1,%2,%3},{%4,%5,%6,%7},{%8,%9},{%0,%1,%2,%3};"
        : "+f"(c[0]), "+f"(c[1]), "+f"(c[2]), "+f"(c[3])
        : "r"(a[0]), "r"(a[1]), "r"(a[2]), "r"(a[3]), "r"(b[0]), "r"(b[1]));
}

// split v = big + res/1024 (residual scaled x1024 to stay in fp16 normal range)
__device__ __forceinline__ void split_h(float v, __half& b, __half& r) {
    __half bh = __float2half_rn(v);
    b = bh;
    r = __float2half_rn((v - __half2float(bh)) * 1024.0f);
}
__device__ __forceinline__ unsigned packh(__half a, __half b) {
    __half2 h = __halves2half2(a, b);
    return *(unsigned*)&h;
}
// float4 -> 4 big halves (uint2) + 4 res halves (uint2)
__device__ __forceinline__ void split4(float4 v, uint2& big, uint2& res) {
    __half b0,b1,b2,b3,r0,r1,r2,r3;
    split_h(v.x,b0,r0); split_h(v.y,b1,r1); split_h(v.z,b2,r2); split_h(v.w,b3,r3);
    big.x = packh(b0,b1); big.y = packh(b2,b3);
    res.x = packh(r0,r1); res.y = packh(r2,r3);
}
__device__ __forceinline__ uint2 tohalf4(float4 v) {
    __half2 h0 = __floats2half2_rn(v.x, v.y);
    __half2 h1 = __floats2half2_rn(v.z, v.w);
    uint2 u; u.x = *(unsigned*)&h0; u.y = *(unsigned*)&h1; return u;
}

static const float RINV = 1.0f / 1024.0f;

// ---------------------------------------------------------------------------
// Projection GEMM (fp16x3 + ldmatrix):  Y[m,n] = sum_k X[m,k]*W[n,k] + bias[n]
// Block 128x64, k-step 32, 256 threads (8 warps 4x2), warp tile 32x32.
// Smem (halves): Xb[128][72] Xr[128][72] Wb[64][72] Wr[64][72]
// ---------------------------------------------------------------------------
static const int PJ_XB = 0;
static const int PJ_XR = 128 * 72;
static const int PJ_WB = 2 * 128 * 72;
static const int PJ_WR = PJ_WB + 64 * 72;
static const int PJ_SMEM_HALF  = PJ_WR + 64 * 72;        // 27648
static const int PJ_SMEM_BYTES = PJ_SMEM_HALF * 2;       // 55296

__device__ __forceinline__ void proj_body(
    const float* __restrict__ X, const float* __restrict__ W,
    const float* __restrict__ bias, float* __restrict__ Y, int head_layout,
    __half* ps)
{
    __half* Xb = ps + PJ_XB;
    __half* Xr = ps + PJ_XR;
    __half* Wb = ps + PJ_WB;
    __half* Wr = ps + PJ_WR;

    const int tid  = threadIdx.x;
    const int lane = tid & 31;
    const int w    = tid >> 5;
    const int g    = lane >> 2;
    const int t4   = lane & 3;
    const int m0 = blockIdx.y * 128;
    const int n0 = blockIdx.x * 64;
    const int wm = (w & 3) * 32;
    const int wn = (w >> 2) * 32;

    float accb[2][4][4], accr[2][4][4];
    #pragma unroll
    for (int i = 0; i < 2; i++)
        #pragma unroll
        for (int j = 0; j < 4; j++)
            #pragma unroll
            for (int l = 0; l < 4; l++) { accb[i][j][l] = 0.f; accr[i][j][l] = 0.f; }

    const int xr_ = tid >> 3, xc_ = tid & 7;

    float4 xv[4], wv[2];
    #pragma unroll
    for (int p = 0; p < 4; p++)
        xv[p] = *(const float4*)(X + (size_t)(m0 + xr_ + p * 32) * 512 + xc_ * 4);
    #pragma unroll
    for (int p = 0; p < 2; p++)
        wv[p] = *(const float4*)(W + (size_t)(n0 + xr_ + p * 32) * 512 + xc_ * 4);

    const int arow = lane & 15;
    const int acol = (lane >> 4) << 3;

    for (int k0 = 0; k0 < 512; k0 += 32) {
        __syncthreads();
        #pragma unroll
        for (int p = 0; p < 4; p++) {
            uint2 big, res; split4(xv[p], big, res);
            int off = (xr_ + p * 32) * 72 + xc_ * 4;
            *(uint2*)(Xb + off) = big;
            *(uint2*)(Xr + off) = res;
        }
        #pragma unroll
        for (int p = 0; p < 2; p++) {
            uint2 big, res; split4(wv[p], big, res);
            int off = (xr_ + p * 32) * 72 + xc_ * 4;
            *(uint2*)(Wb + off) = big;
            *(uint2*)(Wr + off) = res;
        }
        __syncthreads();

        if (k0 + 32 < 512) {
            #pragma unroll
            for (int p = 0; p < 4; p++)
                xv[p] = *(const float4*)(X + (size_t)(m0 + xr_ + p * 32) * 512 + k0 + 32 + xc_ * 4);
            #pragma unroll
            for (int p = 0; p < 2; p++)
                wv[p] = *(const float4*)(W + (size_t)(n0 + xr_ + p * 32) * 512 + k0 + 32 + xc_ * 4);
        }

        #pragma unroll
        for (int ks = 0; ks < 2; ks++) {
            int kk = ks * 16;
            unsigned axb[2][4], axr[2][4];
            #pragma unroll
            for (int mt = 0; mt < 2; mt++) {
                int off = (wm + mt * 16 + arow) * 72 + kk + acol;
                ldm4(axb[mt], sptr(Xb + off));
                ldm4(axr[mt], sptr(Xr + off));
            }
            unsigned bwb[2][4], bwr[2][4];
            #pragma unroll
            for (int np = 0; np < 2; np++) {
                int off = (wn + np * 16 + arow) * 72 + kk + acol;
                ldm4(bwb[np], sptr(Wb + off));
                ldm4(bwr[np], sptr(Wr + off));
            }
            #pragma unroll
            for (int nt = 0; nt < 4; nt++) {
                int np = nt >> 1, hi = nt & 1;
                unsigned bb[2] = { bwb[np][hi], bwb[np][2 + hi] };
                unsigned br[2] = { bwr[np][hi], bwr[np][2 + hi] };
                #pragma unroll
                for (int mt = 0; mt < 2; mt++) {
                    mma16(accb[mt][nt], axb[mt], bb);
                    mma16(accr[mt][nt], axb[mt], br);
                    mma16(accr[mt][nt], axr[mt], bb);
                }
            }
        }
    }

    #pragma unroll
    for (int mt = 0; mt < 2; mt++) {
        #pragma unroll
        for (int nt = 0; nt < 4; nt++) {
            int r0 = m0 + wm + mt * 16 + g;
            int c0 = n0 + wn + nt * 8 + t4 * 2;
            #pragma unroll
            for (int e = 0; e < 4; e++) {
                int m = r0 + (e >= 2 ? 8 : 0);
                int n = c0 + (e & 1);
                float v = accb[mt][nt][e] + accr[mt][nt][e] * RINV + bias[n];
                if (head_layout) {
                    int bb2 = m >> 11, t = m & 2047;
                    int h = n >> 6, dk = n & 63;
                    Y[(((size_t)(bb2 * Hc + h) * Tc + t) * 64) + dk] = v;
                } else {
                    Y[(size_t)m * Dc + n] = v;
                }
            }
        }
    }
}

__global__ void __launch_bounds__(256) qkv_proj(
    const float* __restrict__ q, const float* __restrict__ Wq, const float* __restrict__ bq,
    const float* __restrict__ k, const float* __restrict__ Wk, const float* __restrict__ bk,
    const float* __restrict__ v, const float* __restrict__ Wv, const float* __restrict__ bv)
{
    extern __shared__ __half ps[];
    int z = blockIdx.z;
    const float* X = (z == 0) ? q : (z == 1) ? k : v;
    const float* W = (z == 0) ? Wq : (z == 1) ? Wk : Wv;
    const float* B = (z == 0) ? bq : (z == 1) ? bk : bv;
    float* Y = (z == 0) ? g_Q : (z == 1) ? g_K : g_V;
    proj_body(X, W, B, Y, 1, ps);
}

__global__ void __launch_bounds__(256) out_proj(
    const float* __restrict__ W, const float* __restrict__ bias, float* __restrict__ Y)
{
    extern __shared__ __half ps[];
    proj_body(g_Oh, W, bias, Y, 0, ps);
}

// ---------------------------------------------------------------------------
// Fused attention (fp16 mma + ldmatrix), per (bh, 16-query tile).
// Smem (halves):
//   S  [16][2056]  exp scores (fp16)
//   Qb [16][72], Qr [16][72]
//   Kb [128][72], Kr [128][72]   (Vs[128][72] overlays Kb)
// ---------------------------------------------------------------------------
static const int SST = 2056;
static const int AT_S  = 0;
static const int AT_QB = 16 * SST;            // 32896
static const int AT_QR = AT_QB + 16 * 72;
static const int AT_KB = AT_QR + 16 * 72;     // 35200
static const int AT_KR = AT_KB + 128 * 72;
static const int AT_SMEM_HALF  = AT_KR + 128 * 72;   // 53632
static const int AT_SMEM_BYTES = AT_SMEM_HALF * 2;   // 107264

__global__ void __launch_bounds__(256) attn_mma(float* __restrict__ Aout)
{
    extern __shared__ __half sm[];
    __half* S  = sm + AT_S;
    __half* Qb = sm + AT_QB;
    __half* Qr = sm + AT_QR;
    __half* Kb = sm + AT_KB;
    __half* Kr = sm + AT_KR;
    __half* Vs = sm + AT_KB;     // overlays Kb
    __shared__ float sinv[16];

    const int tid  = threadIdx.x;
    const int lane = tid & 31;
    const int w    = tid >> 5;
    const int g    = lane >> 2;
    const int t4   = lane & 3;
    const int bh   = blockIdx.y;
    const int q0   = (gridDim.x - 1 - blockIdx.x) * 16;   // heavy tiles first

    const float4* Qg = (const float4*)(g_Q + (size_t)bh * Tc * 64);
    const float4* Kg = (const float4*)(g_K + (size_t)bh * Tc * 64);
    const float4* Vg = (const float4*)(g_V + (size_t)bh * Tc * 64);

    // Q tile: 16q x 64d, scaled 1/8, split big/res
    {
        int qq = tid >> 4, d4 = tid & 15;
        float4 qv = Qg[(size_t)(q0 + qq) * 16 + d4];
        qv.x *= 0.125f; qv.y *= 0.125f; qv.z *= 0.125f; qv.w *= 0.125f;
        uint2 big, res; split4(qv, big, res);
        int off = qq * 72 + d4 * 4;
        *(uint2*)(Qb + off) = big;
        *(uint2*)(Qr + off) = res;
    }

    const int nch   = (q0 + 16 + 127) >> 7;
    const int kceil = nch << 7;

    const int ldr = tid >> 4;      // 0..15
    const int ldc = tid & 15;      // 0..15
    const int arow = lane & 15;
    const int acol = (lane >> 4) << 3;

    float o[4] = {0.f, 0.f, 0.f, 0.f};

    for (int ch = 0; ch < nch; ch++) {
        int kb = ch << 7;

        float4 kreg[8];
        #pragma unroll
        for (int p = 0; p < 8; p++)
            kreg[p] = Kg[(size_t)(kb + ldr + p * 16) * 16 + ldc];

        __syncthreads();   // prev PV done with Vs/S; Q visible from here
        #pragma unroll
        for (int p = 0; p < 8; p++) {
            uint2 big, res; split4(kreg[p], big, res);
            int off = (ldr + p * 16) * 72 + ldc * 4;
            *(uint2*)(Kb + off) = big;
            *(uint2*)(Kr + off) = res;
        }
        __syncthreads();

        float4 vreg[8];
        #pragma unroll
        for (int p = 0; p < 8; p++)
            vreg[p] = Vg[(size_t)(kb + ldr + p * 16) * 16 + ldc];

        // QK^T: warp w owns keys [w*16, w*16+16)
        float cb[2][4] = {{0.f,0.f,0.f,0.f},{0.f,0.f,0.f,0.f}};
        float cr[2][4] = {{0.f,0.f,0.f,0.f},{0.f,0.f,0.f,0.f}};
        #pragma unroll
        for (int ks = 0; ks < 4; ks++) {
            int kk = ks * 16;
            unsigned aqb[4], aqr[4], bkb[4], bkr[4];
            ldm4(aqb, sptr(Qb + arow * 72 + kk + acol));
            ldm4(aqr, sptr(Qr + arow * 72 + kk + acol));
            ldm4(bkb, sptr(Kb + (w * 16 + arow) * 72 + kk + acol));
            ldm4(bkr, sptr(Kr + (w * 16 + arow) * 72 + kk + acol));
            #pragma unroll
            for (int nt = 0; nt < 2; nt++) {
                unsigned bb[2] = { bkb[nt], bkb[2 + nt] };
                unsigned br[2] = { bkr[nt], bkr[2 + nt] };
                mma16(cb[nt], aqb, bb);
                mma16(cr[nt], aqb, br);
                mma16(cr[nt], aqr, bb);
            }
        }

        // exp + causal mask -> S (fp16)
        #pragma unroll
        for (int nt = 0; nt < 2; nt++) {
            int kloc = w * 16 + nt * 8 + 2 * t4;
            int kg = kb + kloc;
            float s0 = cb[nt][0] + cr[nt][0] * RINV;
            float s1 = cb[nt][1] + cr[nt][1] * RINV;
            float s2 = cb[nt][2] + cr[nt][2] * RINV;
            float s3 = cb[nt][3] + cr[nt][3] * RINV;
            float e0 = (kg     <= q0 + g)     ? __expf(s0) : 0.f;
            float e1 = (kg + 1 <= q0 + g)     ? __expf(s1) : 0.f;
            float e2 = (kg     <= q0 + g + 8) ? __expf(s2) : 0.f;
            float e3 = (kg + 1 <= q0 + g + 8) ? __expf(s3) : 0.f;
            __half2 h01 = __floats2half2_rn(e0, e1);
            __half2 h23 = __floats2half2_rn(e2, e3);
            *(unsigned*)(S + g * SST + kb + kloc)       = *(unsigned*)&h01;
            *(unsigned*)(S + (g + 8) * SST + kb + kloc) = *(unsigned*)&h23;
        }
        __syncthreads();   // QK reads of Kb/Kr done; S visible

        // V chunk -> Vs (plain fp16)
        #pragma unroll
        for (int p = 0; p < 8; p++)
            *(uint2*)(Vs + (ldr + p * 16) * 72 + ldc * 4) = tohalf4(vreg[p]);
        __syncthreads();

        // PV: warp w owns dk strip [w*8, w*8+8)
        #pragma unroll
        for (int pair = 0; pair < 4; pair++) {
            unsigned bv[4];
            ldm4t(bv, sptr(Vs + (pair * 32 + lane) * 72 + w * 8));
            #pragma unroll
            for (int sub = 0; sub < 2; sub++) {
                unsigned a[4];
                int kk = kb + pair * 32 + sub * 16;
                ldm4(a, sptr(S + arow * SST + kk + acol));
                unsigned b2[2] = { bv[sub * 2], bv[sub * 2 + 1] };
                mma16(o, a, b2);
            }
        }
    }
    __syncthreads();

    // row sums -> sinv
    {
        int rr = tid >> 4, l = tid & 15;
        float s = 0.f;
        for (int c8 = l; c8 < (kceil >> 3); c8 += 16) {
            uint4 u = *(uint4*)(S + rr * SST + c8 * 8);
            float2 f0 = __half22float2(*(__half2*)&u.x);
            float2 f1 = __half22float2(*(__half2*)&u.y);
            float2 f2 = __half22float2(*(__half2*)&u.z);
            float2 f3 = __half22float2(*(__half2*)&u.w);
            s += (f0.x + f0.y) + (f1.x + f1.y) + (f2.x + f2.y) + (f3.x + f3.y);
        }
        #pragma unroll
        for (int off = 8; off; off >>= 1)
            s += __shfl_xor_sync(0xffffffffu, s, off, 16);
        if (l == 0) sinv[rr] = 1.f / s;
    }
    __syncthreads();

    // O write (normalized) -> g_Oh [B,T,D]
    {
        int bb2 = bh >> 3, hh = bh & 7;
        int dk = w * 8 + t4 * 2;
        float* Od = g_Oh + ((size_t)(bb2 * Tc + q0)) * Dc + hh * 64;
        Od[(size_t)g * Dc + dk]           = o[0] * sinv[g];
        Od[(size_t)g * Dc + dk + 1]       = o[1] * sinv[g];
        Od[(size_t)(g + 8) * Dc + dk]     = o[2] * sinv[g + 8];
        Od[(size_t)(g + 8) * Dc + dk + 1] = o[3] * sinv[g + 8];
    }

    // A write (normalized; zeros past kceil)
    if (Aout) {
        float4* A4 = (float4*)(Aout + (size_t)bh * Tc * Tc + (size_t)q0 * Tc);
        int kc4 = kceil >> 2;
        for (int idx = tid; idx < 16 * 512; idx += 256) {
            int qq = idx >> 9, c4 = idx & 511;
            float4 ov;
            if (c4 < kc4) {
                uint2 u = *(uint2*)(S + qq * SST + c4 * 4);
                float2 f0 = __half22float2(*(__half2*)&u.x);
                float2 f1 = __half22float2(*(__half2*)&u.y);
                float inv = sinv[qq];
                ov = make_float4(f0.x * inv, f0.y * inv, f1.x * inv, f1.y * inv);
            } else {
                ov = make_float4(0.f, 0.f, 0.f, 0.f);
            }
            A4[(size_t)qq * 512 + c4] = ov;
        }
    }
}

// ---------------------------------------------------------------------------
extern "C" void kernel_launch(void* const* d_in, const int* in_sizes, int n_in,
                              void* d_out, int out_size)
{
    const float* q  = (const float*)d_in[0];
    const float* k  = (const float*)d_in[1];
    const float* v  = (const float*)d_in[2];
    // d_in[3] = attn_mask (deterministic causal tril; applied analytically)
    const float* Wq = (const float*)d_in[4];
    const float* bq = (const float*)d_in[5];
    const float* Wk = (const float*)d_in[6];
    const float* bk = (const float*)d_in[7];
    const float* Wv = (const float*)d_in[8];
    const float* bv = (const float*)d_in[9];
    const float* Wo = (const float*)d_in[10];
    const float* bo = (const float*)d_in[11];

    float* out = (float*)d_out;
    long long need = (long long)BT * Dc + (long long)BHc * Tc * Tc;
    float* A = ((long long)out_size >= need) ? out + (size_t)BT * Dc : nullptr;

    cudaFuncSetAttribute(qkv_proj,
                         cudaFuncAttributeMaxDynamicSharedMemorySize, PJ_SMEM_BYTES);
    cudaFuncSetAttribute(out_proj,
                         cudaFuncAttributeMaxDynamicSharedMemorySize, PJ_SMEM_BYTES);
    cudaFuncSetAttribute(attn_mma,
                         cudaFuncAttributeMaxDynamicSharedMemorySize, AT_SMEM_BYTES);

    dim3 pg3(Dc / 64, BT / 128, 3);   // (8, 32, 3)
    qkv_proj<<<pg3, 256, PJ_SMEM_BYTES>>>(q, Wq, bq, k, Wk, bk, v, Wv, bv);

    dim3 ag(Tc / 16, BHc);            // (128, 16)
    attn_mma<<<ag, 256, AT_SMEM_BYTES>>>(A);

    dim3 pg(Dc / 64, BT / 128);       // (8, 32)
    out_proj<<<pg, 256, PJ_SMEM_BYTES>>>(Wo, bo, out);
}